// round 1
// baseline (speedup 1.0000x reference)
#include <cuda_runtime.h>
#include <cstdint>

#define SEQ 262144
#define HID 20
#define INP 9
#define NG  80      // 4*HID gates per layer
#define RB  8       // x ring slots (power of 2)
#define PD  6       // prefetch distance in steps

__device__ __forceinline__ float sigm_(float x) {
    x = fminf(fmaxf(x, -30.f), 30.f);
    float e = __expf(-x);
    return __fdividef(1.f, 1.f + e);
}
__device__ __forceinline__ float tanh_(float x) {
    x = fminf(fmaxf(x, -15.f), 15.f);
    float e = __expf(-2.f * x);           // finite due to clamp
    return __fdividef(1.f - e, 1.f + e);
}

__device__ __forceinline__ void cpasync4(void* smem_dst, const void* gmem_src) {
    unsigned saddr = (unsigned)__cvta_generic_to_shared(smem_dst);
    asm volatile("cp.async.ca.shared.global [%0], [%1], 4;\n" :: "r"(saddr), "l"(gmem_src));
}
#define CP_COMMIT()  asm volatile("cp.async.commit_group;\n")
#define CP_WAIT(n)   asm volatile("cp.async.wait_group %0;\n" :: "n"(n))

__global__ void __launch_bounds__(224, 1) lstm_scan_kernel(
    const float* __restrict__ x,
    const float* __restrict__ w_ih1, const float* __restrict__ w_hh1, const float* __restrict__ b1,
    const float* __restrict__ w_ih2, const float* __restrict__ w_hh2, const float* __restrict__ b2,
    const float* __restrict__ w_p,  const float* __restrict__ b_p,
    float* __restrict__ out)
{
    __shared__ __align__(16) float xring[RB][12];   // 9 used, padded
    __shared__ __align__(16) float h1buf[2][HID];
    __shared__ __align__(16) float h2buf[2][HID];
    __shared__ float gact1[NG];
    __shared__ float gact2[NG];

    const int tid = threadIdx.x;

    // ---- per-thread resident weights ----
    float wih[20];      // L1 uses 9, L2 uses 20
    float whh[20];
    float bias = 0.f;

    if (tid < 80) {                       // layer-1 gate thread, gate g = tid
        const int g = tid;
        #pragma unroll
        for (int k = 0; k < INP; k++) wih[k] = w_ih1[g * INP + k];
        #pragma unroll
        for (int k = 0; k < HID; k++) whh[k] = w_hh1[g * HID + k];
        bias = b1[g];
    } else if (tid < 160) {               // layer-2 gate thread, gate g = tid-80
        const int g = tid - 80;
        #pragma unroll
        for (int k = 0; k < HID; k++) wih[k] = w_ih2[g * HID + k];
        #pragma unroll
        for (int k = 0; k < HID; k++) whh[k] = w_hh2[g * HID + k];
        bias = b2[g];
    }
    float wp = 0.f;
    if (tid >= 160 && tid < 160 + HID) wp = w_p[tid - 160];
    const float bp = b_p[0];

    float c = 0.f;                        // cell state (unit threads only)

    // ---- init shared state ----
    if (tid < HID) {
        h1buf[0][tid] = 0.f; h1buf[1][tid] = 0.f;
        h2buf[0][tid] = 0.f; h2buf[1][tid] = 0.f;
    }

    // ---- preload x ring: slots 0..PD-1 ----
    if (tid >= 192 && tid < 192 + INP) {
        const int p = tid - 192;
        for (int s = 0; s < PD; s++) {
            cpasync4(&xring[s][p], &x[s * INP + p]);
            CP_COMMIT();
        }
    }
    __syncthreads();

    // ---- main scan: iter t computes h1[t], h2[t-1], out[t-2] ----
    for (int t = 0; t < SEQ + 2; t++) {
        // ---------------- phase 1: gate GEMVs + activations ----------------
        if (tid < 80) {
            if (t < SEQ) {
                const float* xs = xring[t & (RB - 1)];
                const float* hp = h1buf[(t + 1) & 1];   // h1[t-1]
                float acc[4] = {bias, 0.f, 0.f, 0.f};
                #pragma unroll
                for (int k = 0; k < INP; k++) acc[k & 3] = fmaf(wih[k], xs[k], acc[k & 3]);
                #pragma unroll
                for (int k = 0; k < HID; k++) acc[k & 3] = fmaf(whh[k], hp[k], acc[k & 3]);
                float v = (acc[0] + acc[1]) + (acc[2] + acc[3]);
                gact1[tid] = (tid >= 40 && tid < 60) ? tanh_(v) : sigm_(v);
            }
        } else if (tid < 160) {
            if (t >= 1 && t <= SEQ) {       // computing layer-2 step t-1
                const int g = tid - 80;
                const float* h1p = h1buf[(t + 1) & 1];  // h1[t-1]
                const float* h2p = h2buf[t & 1];        // h2[t-2]
                float acc[4] = {bias, 0.f, 0.f, 0.f};
                #pragma unroll
                for (int k = 0; k < HID; k++) acc[k & 3] = fmaf(wih[k], h1p[k], acc[k & 3]);
                #pragma unroll
                for (int k = 0; k < HID; k++) acc[k & 3] = fmaf(whh[k], h2p[k], acc[k & 3]);
                float v = (acc[0] + acc[1]) + (acc[2] + acc[3]);
                gact2[g] = (g >= 40 && g < 60) ? tanh_(v) : sigm_(v);
            }
        } else if (tid < 192) {
            // projection of step t-2 (whole warp 5 executes uniformly)
            if (t >= 2) {
                const int lane = tid - 160;
                float p = (lane < HID) ? wp * h2buf[t & 1][lane] : 0.f;
                #pragma unroll
                for (int off = 16; off; off >>= 1)
                    p += __shfl_down_sync(0xffffffffu, p, off);
                if (lane == 0) out[t - 2] = p + bp;
            }
        } else if (tid < 192 + INP) {
            // prefetch x[t+PD] into ring
            const int p = tid - 192;
            const int tf = t + PD;
            if (tf < SEQ) cpasync4(&xring[tf & (RB - 1)][p], &x[tf * INP + p]);
            CP_COMMIT();
            CP_WAIT(PD - 1);   // guarantees slot t+1 resident before next iter
        }
        __syncthreads();

        // ---------------- phase 2: cell/hidden update ----------------
        if (tid < HID) {
            if (t < SEQ) {
                const int j = tid;
                float fi = gact1[j], ff = gact1[20 + j], fg = gact1[40 + j], fo = gact1[60 + j];
                c = ff * c + fi * fg;
                h1buf[t & 1][j] = fo * tanh_(c);
            }
        } else if (tid >= 80 && tid < 80 + HID) {
            if (t >= 1 && t <= SEQ) {
                const int j = tid - 80;
                float fi = gact2[j], ff = gact2[20 + j], fg = gact2[40 + j], fo = gact2[60 + j];
                c = ff * c + fi * fg;
                h2buf[(t + 1) & 1][j] = fo * tanh_(c);   // h2[t-1]
            }
        }
        __syncthreads();
    }
}

extern "C" void kernel_launch(void* const* d_in, const int* in_sizes, int n_in,
                              void* d_out, int out_size) {
    (void)in_sizes; (void)n_in; (void)out_size;
    lstm_scan_kernel<<<1, 224>>>(
        (const float*)d_in[0],
        (const float*)d_in[1], (const float*)d_in[2], (const float*)d_in[3],
        (const float*)d_in[4], (const float*)d_in[5], (const float*)d_in[6],
        (const float*)d_in[7], (const float*)d_in[8],
        (float*)d_out);
}

// round 2
// speedup vs baseline: 1.4824x; 1.4824x over previous
#include <cuda_runtime.h>
#include <cstdint>

#define SEQ 262144
#define HID 20
#define PF  4       // x prefetch distance (steps)
#define RB  8       // x ring slots

union F2U { float2 f; unsigned long long u; };

__device__ __forceinline__ float2 ffma2(float2 a, float2 b, float2 c) {
    F2U A, B, C, R; A.f = a; B.f = b; C.f = c;
    asm("fma.rn.f32x2 %0, %1, %2, %3;" : "=l"(R.u) : "l"(A.u), "l"(B.u), "l"(C.u));
    return R.f;
}
__device__ __forceinline__ float ex2f(float x) {
    float r; asm("ex2.approx.f32 %0, %1;" : "=f"(r) : "f"(x)); return r;
}
__device__ __forceinline__ float rcpf(float x) {
    float r; asm("rcp.approx.f32 %0, %1;" : "=f"(r) : "f"(x)); return r;
}
// tanh(x) = 2/(1+exp(-2x)) - 1 ; exp via EX2
__device__ __forceinline__ float tanh_fast(float x) {
    return fmaf(rcpf(1.f + ex2f(x * -2.885390082f)), 2.f, -1.f);
}

__global__ void __launch_bounds__(224, 1) lstm_scan_kernel(
    const float* __restrict__ x,
    const float* __restrict__ w_ih1, const float* __restrict__ w_hh1, const float* __restrict__ b1,
    const float* __restrict__ w_ih2, const float* __restrict__ w_hh2, const float* __restrict__ b2,
    const float* __restrict__ w_p,  const float* __restrict__ b_p,
    float* __restrict__ out)
{
    __shared__ __align__(16) float xring[RB][12];   // 9 used, pads zero
    __shared__ __align__(16) float h1buf[2][24];    // 20 used
    __shared__ __align__(16) float h2buf[2][24];

    const int tid  = threadIdx.x;
    const int w    = tid >> 5;
    const int lane = tid & 31;
    const int role = (w < 3) ? 0 : (w < 6) ? 1 : 2;   // 0=L1, 1=L2, 2=proj+x

    // ---- per-lane resident weights ----
    float2 wa[10];   // L1: x-side (5 pairs used, 9+pad) ; L2: h1-side (10 pairs)
    float2 wb[10];   // recurrent h-side (10 pairs)
    float  bias = 0.f, escale = -1.4426950408f, amul = 1.f, aadd = 0.f;
    int    unit = 0, gate = 0;
    const int qbase = lane & ~3;

    if (role < 2) {
        const int wl = (role == 0) ? w : (w - 3);
        unit = wl * 8 + (lane >> 2);       // units 0..23; >=20 are junk lanes
        gate = lane & 3;                   // 0=i 1=f 2=g 3=o
        const int uc = (unit < HID) ? unit : (HID - 1);
        const int r  = gate * HID + uc;    // PyTorch row order i,f,g,o
        if (role == 0) {
            const float* Wx = w_ih1 + r * 9;
            #pragma unroll
            for (int k = 0; k < 4; k++) wa[k] = make_float2(Wx[2*k], Wx[2*k+1]);
            wa[4] = make_float2(Wx[8], 0.f);
            #pragma unroll
            for (int k = 5; k < 10; k++) wa[k] = make_float2(0.f, 0.f);
            const float2* Wh = (const float2*)(w_hh1 + r * HID);
            #pragma unroll
            for (int k = 0; k < 10; k++) wb[k] = Wh[k];
            bias = b1[r];
        } else {
            const float2* Wi = (const float2*)(w_ih2 + r * HID);
            const float2* Wh = (const float2*)(w_hh2 + r * HID);
            #pragma unroll
            for (int k = 0; k < 10; k++) { wa[k] = Wi[k]; wb[k] = Wh[k]; }
            bias = b2[r];
        }
        if (gate == 2) { escale = -2.885390082f; amul = 2.f; aadd = -1.f; }
    }
    float wp = 0.f;
    if (role == 2 && lane < HID) wp = w_p[lane];
    const float bp = b_p[0];

    // ---- zero-init shared ----
    for (int i = tid; i < RB * 12; i += 224) ((float*)xring)[i] = 0.f;
    for (int i = tid; i < 2 * 24; i += 224) { ((float*)h1buf)[i] = 0.f; ((float*)h2buf)[i] = 0.f; }
    __syncthreads();

    // ---- preload x ring (slots 0..PF-1) + pipeline register ----
    float xreg = 0.f;
    if (role == 2 && lane < 9) {
        for (int s = 0; s < PF; s++) xring[s][lane] = x[s * 9 + lane];
        xreg = x[PF * 9 + lane];
    }
    __syncthreads();

    float c = 0.f;   // cell state, redundant per quad

    // iter t: L1 -> h1[t], L2 -> h2[t-1], proj -> out[t-2]
    for (int t = 0; t < SEQ + 2; t++) {
        if (role == 0) {
            if (t < SEQ) {
                const float2* xs = (const float2*)xring[t & (RB - 1)];
                const float2* hp = (const float2*)h1buf[(t + 1) & 1];   // h1[t-1]
                float2 a0 = make_float2(bias, 0.f), a1 = make_float2(0.f, 0.f);
                a0 = ffma2(wa[0], xs[0], a0);  a1 = ffma2(wa[1], xs[1], a1);
                a0 = ffma2(wa[2], xs[2], a0);  a1 = ffma2(wa[3], xs[3], a1);
                a0 = ffma2(wa[4], xs[4], a0);
                #pragma unroll
                for (int k = 0; k < 10; k += 2) {
                    a0 = ffma2(wb[k],   hp[k],   a0);
                    a1 = ffma2(wb[k+1], hp[k+1], a1);
                }
                const float v   = (a0.x + a0.y) + (a1.x + a1.y);
                const float act = fmaf(rcpf(1.f + ex2f(v * escale)), amul, aadd);
                const float gi = __shfl_sync(0xffffffffu, act, qbase);
                const float gf = __shfl_sync(0xffffffffu, act, qbase + 1);
                const float gg = __shfl_sync(0xffffffffu, act, qbase + 2);
                const float go = __shfl_sync(0xffffffffu, act, qbase + 3);
                c = fmaf(gf, c, gi * gg);
                const float h = go * tanh_fast(c);
                if (gate == 0 && unit < HID) h1buf[t & 1][unit] = h;
            }
        } else if (role == 1) {
            if (t >= 1 && t <= SEQ) {
                const float2* h1p = (const float2*)h1buf[(t + 1) & 1];  // h1[t-1]
                const float2* h2p = (const float2*)h2buf[t & 1];        // h2[t-2]
                float2 a0 = make_float2(bias, 0.f), a1 = make_float2(0.f, 0.f);
                #pragma unroll
                for (int k = 0; k < 10; k += 2) {
                    a0 = ffma2(wa[k],   h1p[k],   a0);
                    a1 = ffma2(wa[k+1], h1p[k+1], a1);
                }
                #pragma unroll
                for (int k = 0; k < 10; k += 2) {
                    a0 = ffma2(wb[k],   h2p[k],   a0);
                    a1 = ffma2(wb[k+1], h2p[k+1], a1);
                }
                const float v   = (a0.x + a0.y) + (a1.x + a1.y);
                const float act = fmaf(rcpf(1.f + ex2f(v * escale)), amul, aadd);
                const float gi = __shfl_sync(0xffffffffu, act, qbase);
                const float gf = __shfl_sync(0xffffffffu, act, qbase + 1);
                const float gg = __shfl_sync(0xffffffffu, act, qbase + 2);
                const float go = __shfl_sync(0xffffffffu, act, qbase + 3);
                c = fmaf(gf, c, gi * gg);
                const float h = go * tanh_fast(c);
                if (gate == 0 && unit < HID) h2buf[(t + 1) & 1][unit] = h;  // h2[t-1]
            }
        } else {
            // projection of step t-2
            if (t >= 2) {
                float hv = (lane < HID) ? h2buf[t & 1][lane] : 0.f;
                float p = wp * hv;
                #pragma unroll
                for (int o = 16; o; o >>= 1) p += __shfl_down_sync(0xffffffffu, p, o);
                if (lane == 0) out[t - 2] = p + bp;
            }
            // x streaming: publish x[t+PF], start load of x[t+PF+1]
            const int ts = t + PF;
            if (lane < 9 && ts < SEQ) {
                xring[ts & (RB - 1)][lane] = xreg;
                const int tn = ts + 1;
                if (tn < SEQ) xreg = __ldg(&x[tn * 9 + lane]);
            }
        }
        __syncthreads();
    }
}

extern "C" void kernel_launch(void* const* d_in, const int* in_sizes, int n_in,
                              void* d_out, int out_size) {
    (void)in_sizes; (void)n_in; (void)out_size;
    lstm_scan_kernel<<<1, 224>>>(
        (const float*)d_in[0],
        (const float*)d_in[1], (const float*)d_in[2], (const float*)d_in[3],
        (const float*)d_in[4], (const float*)d_in[5], (const float*)d_in[6],
        (const float*)d_in[7], (const float*)d_in[8],
        (float*)d_out);
}